// round 11
// baseline (speedup 1.0000x reference)
#include <cuda_runtime.h>
#include <cuda_bf16.h>

// Problem constants (fixed shapes per reference)
#define CC 9
#define HH 180
#define WW 240
#define BB 8
#define NN 100000
#define HW (HH * WW)                   // 43200
#define NUM_VOXELS (2 * CC * HW * BB)  // 6220800
#define NCELLS (BB * 2 * HW)           // 691200 (pixel x polarity x batch)
#define CPAD 12                        // bins padded 9 -> 12 (16B alignment)

// Piecewise-linear table of the scalar MLP f(s), s in [-1, 1].
// Lerp error linear in cell width (measured 1.08e-6 @8192, 3.2e-6 @4096,
// 2.7e-5 @1024). TM=4096: 3.2e-6, ~300x under the gate; table = 16KB (L1-fit).
#define TM 4096

#define JP 104                          // w2 row stride in smem (16B-aligned quads)

__device__ float g_table[TM];
// Zero at module load; transpose_kernel re-zeroes each cell after reading,
// so scratch is zero at the start of every launch / graph replay.
__device__ float g_scratch[(size_t)NCELLS * CPAD];   // 33.2 MB

__device__ __forceinline__ float lrelu(float v) {
    return fmaxf(v, 0.1f * v);    // leaky_relu slope 0.1
}

// ---------------------------------------------------------------------------
// Table build: ONE WARP PER 4 SAMPLES, w2 staged in shared.
// Lane l owns hidden cols 4l..4l+3 (lanes 25-31 predicated off).
// Per iteration i: one broadcast LDS.64 of {b1,w1}, one LDS.128 of the w2
// quad (shared by all 4 samples), 4 h-computations + 16 independent FMAs.
// 4x the ILP per load of the one-sample version -> exposed LDS latency /4.
// 128 blocks x 8 warps = 1024 warps for TM=4096.
// ---------------------------------------------------------------------------
#define BT_THREADS 256
#define SPW 4                                    // samples per warp
#define BT_WPB (BT_THREADS / 32)                 // 8 warps per block
#define TBLK (TM / (BT_WPB * SPW))               // 128 blocks

__global__ __launch_bounds__(BT_THREADS) void build_table_kernel(
    const float* __restrict__ w1, const float* __restrict__ b1,
    const float* __restrict__ w2, const float* __restrict__ b2,
    const float* __restrict__ w3, const float* __restrict__ b3)
{
    __shared__ float  sw2[100 * JP];             // [i][j], quad-aligned rows
    __shared__ float2 s_bw1[100];                // {b1[i], w1[i]}

    int tid  = threadIdx.x;
    int lane = tid & 31;
    int wid  = tid >> 5;

    // stage w2 as float4s (global rows are 400B, 16B-aligned)
    for (int f = tid; f < 2500; f += BT_THREADS) {
        float4 v = reinterpret_cast<const float4*>(w2)[f];
        int r = f / 25, c = f - r * 25;
        *reinterpret_cast<float4*>(&sw2[r * JP + c * 4]) = v;
    }
    if (tid < 100) s_bw1[tid] = make_float2(b1[tid], w1[tid]);
    __syncthreads();

    int k0 = (blockIdx.x * BT_WPB + wid) * SPW;  // first sample of this warp
    const float step = 2.0f / (float)(TM - 1);
    float s0 = -1.0f + (float)k0 * step;
    float s1 = s0 + step;
    float s2 = s1 + step;
    float s3 = s2 + step;

    int j0 = lane * 4;
    bool active = (lane < 25);

    float a00=0.f,a01=0.f,a02=0.f,a03=0.f;   // sample 0, cols 0..3
    float a10=0.f,a11=0.f,a12=0.f,a13=0.f;
    float a20=0.f,a21=0.f,a22=0.f,a23=0.f;
    float a30=0.f,a31=0.f,a32=0.f,a33=0.f;
    if (active) {
        float4 bb = *reinterpret_cast<const float4*>(b2 + j0);
        a00=bb.x; a01=bb.y; a02=bb.z; a03=bb.w;
        a10=bb.x; a11=bb.y; a12=bb.z; a13=bb.w;
        a20=bb.x; a21=bb.y; a22=bb.z; a23=bb.w;
        a30=bb.x; a31=bb.y; a32=bb.z; a33=bb.w;
    }

#pragma unroll 4
    for (int i = 0; i < 100; i++) {
        float2 bw = s_bw1[i];                    // broadcast
        float h0 = lrelu(fmaf(s0, bw.y, bw.x));
        float h1 = lrelu(fmaf(s1, bw.y, bw.x));
        float h2 = lrelu(fmaf(s2, bw.y, bw.x));
        float h3 = lrelu(fmaf(s3, bw.y, bw.x));
        if (active) {
            float4 w = *reinterpret_cast<const float4*>(&sw2[i * JP + j0]);
            a00 = fmaf(h0, w.x, a00); a01 = fmaf(h0, w.y, a01);
            a02 = fmaf(h0, w.z, a02); a03 = fmaf(h0, w.w, a03);
            a10 = fmaf(h1, w.x, a10); a11 = fmaf(h1, w.y, a11);
            a12 = fmaf(h1, w.z, a12); a13 = fmaf(h1, w.w, a13);
            a20 = fmaf(h2, w.x, a20); a21 = fmaf(h2, w.y, a21);
            a22 = fmaf(h2, w.z, a22); a23 = fmaf(h2, w.w, a23);
            a30 = fmaf(h3, w.x, a30); a31 = fmaf(h3, w.y, a31);
            a32 = fmaf(h3, w.z, a32); a33 = fmaf(h3, w.w, a33);
        }
    }

    float p0 = 0.f, p1 = 0.f, p2 = 0.f, p3 = 0.f;
    if (active) {
        float4 wv = *reinterpret_cast<const float4*>(w3 + j0);
        p0 = lrelu(a00)*wv.x + lrelu(a01)*wv.y + lrelu(a02)*wv.z + lrelu(a03)*wv.w;
        p1 = lrelu(a10)*wv.x + lrelu(a11)*wv.y + lrelu(a12)*wv.z + lrelu(a13)*wv.w;
        p2 = lrelu(a20)*wv.x + lrelu(a21)*wv.y + lrelu(a22)*wv.z + lrelu(a23)*wv.w;
        p3 = lrelu(a30)*wv.x + lrelu(a31)*wv.y + lrelu(a32)*wv.z + lrelu(a33)*wv.w;
    }

#pragma unroll
    for (int d = 16; d >= 1; d >>= 1) {
        p0 += __shfl_xor_sync(0xffffffffu, p0, d);
        p1 += __shfl_xor_sync(0xffffffffu, p1, d);
        p2 += __shfl_xor_sync(0xffffffffu, p2, d);
        p3 += __shfl_xor_sync(0xffffffffu, p3, d);
    }

    if (lane == 0) {
        float bias = b3[0];
        g_table[k0 + 0] = p0 + bias;
        g_table[k0 + 1] = p1 + bias;
        g_table[k0 + 2] = p2 + bias;
        g_table[k0 + 3] = p3 + bias;
    }
}

// ---------------------------------------------------------------------------
// Scatter: one thread per event. 9 bin-values via table lerp, accumulated
// into bin-CONTIGUOUS scratch with 2x red.v4 + 1 scalar RED (3 lanes/event,
// one 128B line). cell = x + W*y + HW*(p + 2*b).
// ---------------------------------------------------------------------------
__global__ __launch_bounds__(256) void scatter_kernel(
    const float* __restrict__ t, const int* __restrict__ x,
    const int* __restrict__ y, const int* __restrict__ p,
    int total)
{
    int e = blockIdx.x * blockDim.x + threadIdx.x;
    if (e >= total) return;

    float tf = t[e];
    int b = e / NN;
    int cell = x[e] + WW * y[e] + HW * (p[e] + 2 * b);
    float* dst = g_scratch + (size_t)cell * CPAD;

    const float scale = (float)(TM - 1) * 0.5f;

    float v[9];
#pragma unroll
    for (int i = 0; i < CC; i++) {
        float s = tf - (float)i * 0.125f;     // i/(C-1), C-1 = 8
        float fi = (s + 1.0f) * scale;
        int i0 = (int)fi;
        i0 = max(0, min(i0, TM - 2));
        float fr = fi - (float)i0;
        float f0 = g_table[i0];
        float f1 = g_table[i0 + 1];
        v[i] = tf * fmaf(f1 - f0, fr, f0);
    }

    asm volatile("red.global.add.v4.f32 [%0], {%1,%2,%3,%4};"
                 :: "l"(dst), "f"(v[0]), "f"(v[1]), "f"(v[2]), "f"(v[3])
                 : "memory");
    asm volatile("red.global.add.v4.f32 [%0], {%1,%2,%3,%4};"
                 :: "l"(dst + 4), "f"(v[4]), "f"(v[5]), "f"(v[6]), "f"(v[7])
                 : "memory");
    atomicAdd(dst + 8, v[8]);
}

// ---------------------------------------------------------------------------
// Transpose + scratch reset: scratch[cell][c] -> out[(q*C + c)*HW + pix],
// q = cell/HW = p + 2b — exactly the reference's concatenated output layout.
// The cell is zeroed after reading so the next launch/replay starts clean
// (measured cheaper than any separate/fused zeroing scheme).
// ---------------------------------------------------------------------------
__global__ __launch_bounds__(256) void transpose_kernel(float* __restrict__ out)
{
    int cell = blockIdx.x * blockDim.x + threadIdx.x;   // < NCELLS exactly
    float4* src = reinterpret_cast<float4*>(g_scratch + (size_t)cell * CPAD);
    float4 a  = src[0];
    float4 c4 = src[1];
    float4 c8 = src[2];   // .x = bin 8, rest padding

    float4 z = make_float4(0.f, 0.f, 0.f, 0.f);
    src[0] = z; src[1] = z; src[2] = z;

    int q   = cell / HW;
    int pix = cell - q * HW;
    float* o = out + (size_t)q * CC * HW + pix;

    o[0 * HW] = a.x;  o[1 * HW] = a.y;  o[2 * HW] = a.z;  o[3 * HW] = a.w;
    o[4 * HW] = c4.x; o[5 * HW] = c4.y; o[6 * HW] = c4.z; o[7 * HW] = c4.w;
    o[8 * HW] = c8.x;
}

// ---------------------------------------------------------------------------
// Launch.  metadata order: t, w1, b1, w2, b2, w3, b3, x, y, p
// ---------------------------------------------------------------------------
extern "C" void kernel_launch(void* const* d_in, const int* in_sizes, int n_in,
                              void* d_out, int out_size)
{
    const float* t  = (const float*)d_in[0];
    const float* w1 = (const float*)d_in[1];
    const float* b1 = (const float*)d_in[2];
    const float* w2 = (const float*)d_in[3];
    const float* b2 = (const float*)d_in[4];
    const float* w3 = (const float*)d_in[5];
    const float* b3 = (const float*)d_in[6];
    const int*   x  = (const int*)d_in[7];
    const int*   y  = (const int*)d_in[8];
    const int*   p  = (const int*)d_in[9];
    float* out = (float*)d_out;

    int total = in_sizes[0];          // B*N = 800000

    build_table_kernel<<<TBLK, BT_THREADS>>>(w1, b1, w2, b2, w3, b3);
    scatter_kernel<<<(total + 255) / 256, 256>>>(t, x, y, p, total);
    transpose_kernel<<<NCELLS / 256, 256>>>(out);
}

// round 14
// speedup vs baseline: 1.1777x; 1.1777x over previous
#include <cuda_runtime.h>
#include <cuda_bf16.h>

// Problem constants (fixed shapes per reference)
#define CC 9
#define HH 180
#define WW 240
#define BB 8
#define NN 100000
#define HW (HH * WW)                   // 43200
#define NUM_VOXELS (2 * CC * HW * BB)  // 6220800
#define NCELLS (BB * 2 * HW)           // 691200 (pixel x polarity x batch)
#define CPAD 12                        // bins padded 9 -> 12 (16B alignment)

// Piecewise-linear table of the scalar MLP f(s), s in [-1, 1].
// Lerp error linear in cell width (measured 3.2e-6 @4096, 2.7e-5 @1024).
// TM=1024: 4KB table -> cheap smem staging in scatter, 37x margin.
#define TM 1024

#define JP 104                          // w2 row stride in smem (16B-aligned quads)

__device__ float g_table[TM];
// Zero at module load; transpose_kernel re-zeroes each cell after reading,
// so scratch is zero at the start of every launch / graph replay.
__device__ float g_scratch[(size_t)NCELLS * CPAD];   // 33.2 MB

__device__ __forceinline__ float lrelu(float v) {
    return fmaxf(v, 0.1f * v);    // leaky_relu slope 0.1
}

// ---------------------------------------------------------------------------
// Table build: ONE WARP PER 2 SAMPLES, w2 staged in shared.
// Lane l owns hidden cols 4l..4l+3 (lanes 25-31 predicated off).
// Per iteration: broadcast LDS.64 of {b1,w1}, LDS.128 of the w2 quad
// (shared by both samples), 2 h-computations + 8 independent FMAs.
// 64 blocks x 8 warps = 512 warps for TM=1024; 2 warps/SMSP interleave.
// ---------------------------------------------------------------------------
#define BT_THREADS 256
#define SPW 2                                    // samples per warp
#define BT_WPB (BT_THREADS / 32)                 // 8 warps per block
#define TBLK (TM / (BT_WPB * SPW))               // 64 blocks

__global__ __launch_bounds__(BT_THREADS) void build_table_kernel(
    const float* __restrict__ w1, const float* __restrict__ b1,
    const float* __restrict__ w2, const float* __restrict__ b2,
    const float* __restrict__ w3, const float* __restrict__ b3)
{
    __shared__ float  sw2[100 * JP];             // [i][j], quad-aligned rows
    __shared__ float2 s_bw1[100];                // {b1[i], w1[i]}

    int tid  = threadIdx.x;
    int lane = tid & 31;
    int wid  = tid >> 5;

    // stage w2 as float4s (global rows are 400B, 16B-aligned)
    for (int f = tid; f < 2500; f += BT_THREADS) {
        float4 v = reinterpret_cast<const float4*>(w2)[f];
        int r = f / 25, c = f - r * 25;
        *reinterpret_cast<float4*>(&sw2[r * JP + c * 4]) = v;
    }
    if (tid < 100) s_bw1[tid] = make_float2(b1[tid], w1[tid]);
    __syncthreads();

    int k0 = (blockIdx.x * BT_WPB + wid) * SPW;  // first sample of this warp
    const float step = 2.0f / (float)(TM - 1);
    float s0 = -1.0f + (float)k0 * step;
    float s1 = s0 + step;

    int j0 = lane * 4;
    bool active = (lane < 25);

    float a00=0.f,a01=0.f,a02=0.f,a03=0.f;   // sample 0
    float a10=0.f,a11=0.f,a12=0.f,a13=0.f;   // sample 1
    if (active) {
        float4 bb = *reinterpret_cast<const float4*>(b2 + j0);
        a00=bb.x; a01=bb.y; a02=bb.z; a03=bb.w;
        a10=bb.x; a11=bb.y; a12=bb.z; a13=bb.w;
    }

#pragma unroll 5
    for (int i = 0; i < 100; i++) {
        float2 bw = s_bw1[i];                    // broadcast
        float h0 = lrelu(fmaf(s0, bw.y, bw.x));
        float h1 = lrelu(fmaf(s1, bw.y, bw.x));
        if (active) {
            float4 w = *reinterpret_cast<const float4*>(&sw2[i * JP + j0]);
            a00 = fmaf(h0, w.x, a00); a01 = fmaf(h0, w.y, a01);
            a02 = fmaf(h0, w.z, a02); a03 = fmaf(h0, w.w, a03);
            a10 = fmaf(h1, w.x, a10); a11 = fmaf(h1, w.y, a11);
            a12 = fmaf(h1, w.z, a12); a13 = fmaf(h1, w.w, a13);
        }
    }

    float p0 = 0.f, p1 = 0.f;
    if (active) {
        float4 wv = *reinterpret_cast<const float4*>(w3 + j0);
        p0 = lrelu(a00)*wv.x + lrelu(a01)*wv.y + lrelu(a02)*wv.z + lrelu(a03)*wv.w;
        p1 = lrelu(a10)*wv.x + lrelu(a11)*wv.y + lrelu(a12)*wv.z + lrelu(a13)*wv.w;
    }

#pragma unroll
    for (int d = 16; d >= 1; d >>= 1) {
        p0 += __shfl_xor_sync(0xffffffffu, p0, d);
        p1 += __shfl_xor_sync(0xffffffffu, p1, d);
    }

    if (lane == 0) {
        float bias = b3[0];
        g_table[k0 + 0] = p0 + bias;
        g_table[k0 + 1] = p1 + bias;
    }
}

// ---------------------------------------------------------------------------
// Scatter: one thread per event. Table staged into SHARED (4KB, one float4
// per thread) — random lookups via LDS (conflict-degree ~4) instead of
// L1tex wavefronts (~20/load for random lanes). 9 bin-values, accumulated
// into bin-CONTIGUOUS scratch with 2x red.v4 + 1 scalar RED (3 lanes/event).
// cell = x + W*y + HW*(p + 2*b). Grid covers total exactly (800000 = 3125*256).
// ---------------------------------------------------------------------------
__global__ __launch_bounds__(256) void scatter_kernel(
    const float* __restrict__ t, const int* __restrict__ x,
    const int* __restrict__ y, const int* __restrict__ p,
    int total)
{
    __shared__ float s_tab[TM];

    int tid = threadIdx.x;
    // stage table: 1024 floats, 1 float4 per thread
    reinterpret_cast<float4*>(s_tab)[tid & 255] =
        reinterpret_cast<const float4*>(g_table)[tid & 255];
    __syncthreads();

    int e = blockIdx.x * blockDim.x + tid;
    if (e >= total) return;

    float tf = t[e];
    int b = e / NN;
    int cell = x[e] + WW * y[e] + HW * (p[e] + 2 * b);
    float* dst = g_scratch + (size_t)cell * CPAD;

    const float scale = (float)(TM - 1) * 0.5f;

    float v[9];
#pragma unroll
    for (int i = 0; i < CC; i++) {
        float s = tf - (float)i * 0.125f;     // i/(C-1), C-1 = 8
        float fi = (s + 1.0f) * scale;
        int i0 = (int)fi;
        i0 = max(0, min(i0, TM - 2));
        float fr = fi - (float)i0;
        float f0 = s_tab[i0];
        float f1 = s_tab[i0 + 1];
        v[i] = tf * fmaf(f1 - f0, fr, f0);
    }

    asm volatile("red.global.add.v4.f32 [%0], {%1,%2,%3,%4};"
                 :: "l"(dst), "f"(v[0]), "f"(v[1]), "f"(v[2]), "f"(v[3])
                 : "memory");
    asm volatile("red.global.add.v4.f32 [%0], {%1,%2,%3,%4};"
                 :: "l"(dst + 4), "f"(v[4]), "f"(v[5]), "f"(v[6]), "f"(v[7])
                 : "memory");
    atomicAdd(dst + 8, v[8]);
}

// ---------------------------------------------------------------------------
// Transpose + scratch reset: scratch[cell][c] -> out[(q*C + c)*HW + pix],
// q = cell/HW = p + 2b — exactly the reference's concatenated output layout.
// The cell is zeroed after reading so the next launch/replay starts clean.
// ---------------------------------------------------------------------------
__global__ __launch_bounds__(256) void transpose_kernel(float* __restrict__ out)
{
    int cell = blockIdx.x * blockDim.x + threadIdx.x;   // < NCELLS exactly
    float4* src = reinterpret_cast<float4*>(g_scratch + (size_t)cell * CPAD);
    float4 a  = src[0];
    float4 c4 = src[1];
    float4 c8 = src[2];   // .x = bin 8, rest padding

    float4 z = make_float4(0.f, 0.f, 0.f, 0.f);
    src[0] = z; src[1] = z; src[2] = z;

    int q   = cell / HW;
    int pix = cell - q * HW;
    float* o = out + (size_t)q * CC * HW + pix;

    o[0 * HW] = a.x;  o[1 * HW] = a.y;  o[2 * HW] = a.z;  o[3 * HW] = a.w;
    o[4 * HW] = c4.x; o[5 * HW] = c4.y; o[6 * HW] = c4.z; o[7 * HW] = c4.w;
    o[8 * HW] = c8.x;
}

// ---------------------------------------------------------------------------
// Launch.  metadata order: t, w1, b1, w2, b2, w3, b3, x, y, p
// ---------------------------------------------------------------------------
extern "C" void kernel_launch(void* const* d_in, const int* in_sizes, int n_in,
                              void* d_out, int out_size)
{
    const float* t  = (const float*)d_in[0];
    const float* w1 = (const float*)d_in[1];
    const float* b1 = (const float*)d_in[2];
    const float* w2 = (const float*)d_in[3];
    const float* b2 = (const float*)d_in[4];
    const float* w3 = (const float*)d_in[5];
    const float* b3 = (const float*)d_in[6];
    const int*   x  = (const int*)d_in[7];
    const int*   y  = (const int*)d_in[8];
    const int*   p  = (const int*)d_in[9];
    float* out = (float*)d_out;

    int total = in_sizes[0];          // B*N = 800000

    build_table_kernel<<<TBLK, BT_THREADS>>>(w1, b1, w2, b2, w3, b3);
    scatter_kernel<<<(total + 255) / 256, 256>>>(t, x, y, p, total);
    transpose_kernel<<<NCELLS / 256, 256>>>(out);
}

// round 15
// speedup vs baseline: 1.3353x; 1.1338x over previous
#include <cuda_runtime.h>
#include <cuda_bf16.h>

// Problem constants (fixed shapes per reference)
#define CC 9
#define HH 180
#define WW 240
#define BB 8
#define NN 100000
#define HW (HH * WW)                   // 43200
#define NUM_VOXELS (2 * CC * HW * BB)  // 6220800
#define NCELLS (BB * 2 * HW)           // 691200 (pixel x polarity x batch)
#define CPAD 12                        // bins padded 9 -> 12 (16B alignment)

// Piecewise-linear table of the scalar MLP f(s), s in [-1, 1].
// Lerp error linear in cell width (measured 3.2e-6 @4096, 2.7e-5 @1024).
#define TM 1024

__device__ float g_table[TM];
// Zero at module load; transpose_kernel re-zeroes each cell after reading,
// so scratch is zero at the start of every launch / graph replay.
__device__ float g_scratch[(size_t)NCELLS * CPAD];   // 33.2 MB

__device__ __forceinline__ float lrelu(float v) {
    return fmaxf(v, 0.1f * v);    // leaky_relu slope 0.1
}

// ---------------------------------------------------------------------------
// Table build: ONE BLOCK PER 2 SAMPLES, 512 blocks, NO bulk smem staging.
// Phase 0: threads 0-99 compute h[sample][i] into smem.
// Phase 1: thread (ic = t/25, jq = t%25) accumulates a 4-wide j-quad over a
//          10-wide i-chunk; w2 quads read directly from global (coalesced,
//          L2-hot: 512 blocks x 40KB = 20MB ≈ 2us chip-wide).
// Phase 2: thread j sums 10 i-chunk partials, applies lrelu*w3; butterfly +
//          smem reduce; thread 0 writes both table entries.
// Critical path per block ~1K cyc; 512 blocks saturate the chip.
// ---------------------------------------------------------------------------
#define BT_THREADS 256
#define TBLK (TM / 2)                  // 512 blocks

__global__ __launch_bounds__(BT_THREADS) void build_table_kernel(
    const float* __restrict__ w1, const float* __restrict__ b1,
    const float* __restrict__ w2, const float* __restrict__ b2,
    const float* __restrict__ w3, const float* __restrict__ b3)
{
    __shared__ float s_h[2][112];          // h[sample][i]
    __shared__ float s_part[2][10][104];   // partial a[sample][i-chunk][j]
    __shared__ float s_red[2][4];

    int tid = threadIdx.x;
    int k0 = blockIdx.x * 2;
    const float step = 2.0f / (float)(TM - 1);
    float s0 = -1.0f + (float)k0 * step;
    float s1 = s0 + step;

    // Phase 0: hidden layer 1 for both samples
    if (tid < 100) {
        float wv = w1[tid], bv = b1[tid];
        s_h[0][tid] = lrelu(fmaf(s0, wv, bv));
        s_h[1][tid] = lrelu(fmaf(s1, wv, bv));
    }
    __syncthreads();

    // Phase 1: partial matvec (250 threads active)
    int jq = tid % 25;
    int ic = tid / 25;
    if (ic < 10) {
        int j0 = jq * 4;
        float a00=0.f,a01=0.f,a02=0.f,a03=0.f;
        float a10=0.f,a11=0.f,a12=0.f,a13=0.f;
        int ibase = ic * 10;
#pragma unroll
        for (int ii = 0; ii < 10; ii++) {
            int i = ibase + ii;
            float h0 = s_h[0][i];
            float h1 = s_h[1][i];
            float4 w = *reinterpret_cast<const float4*>(w2 + i * 100 + j0);
            a00 = fmaf(h0, w.x, a00); a01 = fmaf(h0, w.y, a01);
            a02 = fmaf(h0, w.z, a02); a03 = fmaf(h0, w.w, a03);
            a10 = fmaf(h1, w.x, a10); a11 = fmaf(h1, w.y, a11);
            a12 = fmaf(h1, w.z, a12); a13 = fmaf(h1, w.w, a13);
        }
        *reinterpret_cast<float4*>(&s_part[0][ic][j0]) = make_float4(a00,a01,a02,a03);
        *reinterpret_cast<float4*>(&s_part[1][ic][j0]) = make_float4(a10,a11,a12,a13);
    }
    __syncthreads();

    // Phase 2: per-j sum over i-chunks, layer-2 nonlinearity + w3, reduce
    float g0 = 0.f, g1 = 0.f;
    if (tid < 100) {
        float a0 = b2[tid];
        float a1 = a0;
#pragma unroll
        for (int c = 0; c < 10; c++) {
            a0 += s_part[0][c][tid];
            a1 += s_part[1][c][tid];
        }
        float wv = w3[tid];
        g0 = lrelu(a0) * wv;
        g1 = lrelu(a1) * wv;
    }
#pragma unroll
    for (int d = 16; d >= 1; d >>= 1) {
        g0 += __shfl_xor_sync(0xffffffffu, g0, d);
        g1 += __shfl_xor_sync(0xffffffffu, g1, d);
    }
    int wid = tid >> 5, lane = tid & 31;
    if (lane == 0 && wid < 4) { s_red[0][wid] = g0; s_red[1][wid] = g1; }
    __syncthreads();
    if (tid == 0) {
        float bias = b3[0];
        g_table[k0 + 0] = s_red[0][0] + s_red[0][1] + s_red[0][2] + s_red[0][3] + bias;
        g_table[k0 + 1] = s_red[1][0] + s_red[1][1] + s_red[1][2] + s_red[1][3] + bias;
    }
}

// ---------------------------------------------------------------------------
// Scatter: one thread per event. Table staged into SHARED (4KB) — random
// lookups via LDS instead of L1tex wavefronts. 9 bin-values, accumulated
// into bin-CONTIGUOUS scratch with 2x red.v4 + 1 scalar RED (3 lanes/event).
// cell = x + W*y + HW*(p + 2*b).
// ---------------------------------------------------------------------------
__global__ __launch_bounds__(256) void scatter_kernel(
    const float* __restrict__ t, const int* __restrict__ x,
    const int* __restrict__ y, const int* __restrict__ p,
    int total)
{
    __shared__ float s_tab[TM];

    int tid = threadIdx.x;
    reinterpret_cast<float4*>(s_tab)[tid & 255] =
        reinterpret_cast<const float4*>(g_table)[tid & 255];
    __syncthreads();

    int e = blockIdx.x * blockDim.x + tid;
    if (e >= total) return;

    float tf = t[e];
    int b = e / NN;
    int cell = x[e] + WW * y[e] + HW * (p[e] + 2 * b);
    float* dst = g_scratch + (size_t)cell * CPAD;

    const float scale = (float)(TM - 1) * 0.5f;

    float v[9];
#pragma unroll
    for (int i = 0; i < CC; i++) {
        float s = tf - (float)i * 0.125f;     // i/(C-1), C-1 = 8
        float fi = (s + 1.0f) * scale;
        int i0 = (int)fi;
        i0 = max(0, min(i0, TM - 2));
        float fr = fi - (float)i0;
        float f0 = s_tab[i0];
        float f1 = s_tab[i0 + 1];
        v[i] = tf * fmaf(f1 - f0, fr, f0);
    }

    asm volatile("red.global.add.v4.f32 [%0], {%1,%2,%3,%4};"
                 :: "l"(dst), "f"(v[0]), "f"(v[1]), "f"(v[2]), "f"(v[3])
                 : "memory");
    asm volatile("red.global.add.v4.f32 [%0], {%1,%2,%3,%4};"
                 :: "l"(dst + 4), "f"(v[4]), "f"(v[5]), "f"(v[6]), "f"(v[7])
                 : "memory");
    atomicAdd(dst + 8, v[8]);
}

// ---------------------------------------------------------------------------
// Transpose + scratch reset: scratch[cell][c] -> out[(q*C + c)*HW + pix],
// q = cell/HW = p + 2b — exactly the reference's concatenated output layout.
// The cell is zeroed after reading so the next launch/replay starts clean.
// ---------------------------------------------------------------------------
__global__ __launch_bounds__(256) void transpose_kernel(float* __restrict__ out)
{
    int cell = blockIdx.x * blockDim.x + threadIdx.x;   // < NCELLS exactly
    float4* src = reinterpret_cast<float4*>(g_scratch + (size_t)cell * CPAD);
    float4 a  = src[0];
    float4 c4 = src[1];
    float4 c8 = src[2];   // .x = bin 8, rest padding

    float4 z = make_float4(0.f, 0.f, 0.f, 0.f);
    src[0] = z; src[1] = z; src[2] = z;

    int q   = cell / HW;
    int pix = cell - q * HW;
    float* o = out + (size_t)q * CC * HW + pix;

    o[0 * HW] = a.x;  o[1 * HW] = a.y;  o[2 * HW] = a.z;  o[3 * HW] = a.w;
    o[4 * HW] = c4.x; o[5 * HW] = c4.y; o[6 * HW] = c4.z; o[7 * HW] = c4.w;
    o[8 * HW] = c8.x;
}

// ---------------------------------------------------------------------------
// Launch.  metadata order: t, w1, b1, w2, b2, w3, b3, x, y, p
// ---------------------------------------------------------------------------
extern "C" void kernel_launch(void* const* d_in, const int* in_sizes, int n_in,
                              void* d_out, int out_size)
{
    const float* t  = (const float*)d_in[0];
    const float* w1 = (const float*)d_in[1];
    const float* b1 = (const float*)d_in[2];
    const float* w2 = (const float*)d_in[3];
    const float* b2 = (const float*)d_in[4];
    const float* w3 = (const float*)d_in[5];
    const float* b3 = (const float*)d_in[6];
    const int*   x  = (const int*)d_in[7];
    const int*   y  = (const int*)d_in[8];
    const int*   p  = (const int*)d_in[9];
    float* out = (float*)d_out;

    int total = in_sizes[0];          // B*N = 800000

    build_table_kernel<<<TBLK, BT_THREADS>>>(w1, b1, w2, b2, w3, b3);
    scatter_kernel<<<(total + 255) / 256, 256>>>(t, x, y, p, total);
    transpose_kernel<<<NCELLS / 256, 256>>>(out);
}

// round 16
// speedup vs baseline: 1.3926x; 1.0429x over previous
#include <cuda_runtime.h>
#include <cuda_bf16.h>

// Problem constants (fixed shapes per reference)
#define CC 9
#define HH 180
#define WW 240
#define BB 8
#define NN 100000
#define HW (HH * WW)                   // 43200
#define NUM_VOXELS (2 * CC * HW * BB)  // 6220800
#define NCELLS (BB * 2 * HW)           // 691200 (pixel x polarity x batch)
#define CPAD 12                        // bins padded 9 -> 12 (16B alignment)

// Piecewise-linear table of the scalar MLP f(s), s in [-1, 1].
// Lerp error linear in cell width (measured 3.2e-6 @4096, 2.7e-5 @1024).
#define TM 1024

__device__ float g_table[TM];
// Zero at module load; transpose_kernel re-zeroes each cell after reading,
// so scratch is zero at the start of every launch / graph replay.
__device__ float g_scratch[(size_t)NCELLS * CPAD];   // 33.2 MB

__device__ __forceinline__ float lrelu(float v) {
    return fmaxf(v, 0.1f * v);    // leaky_relu slope 0.1
}

__device__ __forceinline__ void pdl_wait() {
    asm volatile("griddepcontrol.wait;" ::: "memory");
}
__device__ __forceinline__ void pdl_trigger() {
    asm volatile("griddepcontrol.launch_dependents;");
}

// ---------------------------------------------------------------------------
// Table build: ONE BLOCK PER 2 SAMPLES, 512 blocks, phase-decomposed.
// Phase 0: threads 0-99 compute h[sample][i] into smem.
// Phase 1: thread (ic, jq) accumulates a 4-wide j-quad over a 10-wide
//          i-chunk; w2 read directly from global (coalesced, L2-hot).
// Phase 2: per-j sum over chunks, lrelu*w3, butterfly + smem reduce.
// ---------------------------------------------------------------------------
#define BT_THREADS 256
#define TBLK (TM / 2)                  // 512 blocks

__global__ __launch_bounds__(BT_THREADS) void build_table_kernel(
    const float* __restrict__ w1, const float* __restrict__ b1,
    const float* __restrict__ w2, const float* __restrict__ b2,
    const float* __restrict__ w3, const float* __restrict__ b3)
{
    __shared__ float s_h[2][112];          // h[sample][i]
    __shared__ float s_part[2][10][104];   // partial a[sample][i-chunk][j]
    __shared__ float s_red[2][4];

    int tid = threadIdx.x;
    int k0 = blockIdx.x * 2;
    const float step = 2.0f / (float)(TM - 1);
    float s0 = -1.0f + (float)k0 * step;
    float s1 = s0 + step;

    // Phase 0: hidden layer 1 for both samples
    if (tid < 100) {
        float wv = w1[tid], bv = b1[tid];
        s_h[0][tid] = lrelu(fmaf(s0, wv, bv));
        s_h[1][tid] = lrelu(fmaf(s1, wv, bv));
    }
    __syncthreads();

    // Phase 1: partial matvec (250 threads active)
    int jq = tid % 25;
    int ic = tid / 25;
    if (ic < 10) {
        int j0 = jq * 4;
        float a00=0.f,a01=0.f,a02=0.f,a03=0.f;
        float a10=0.f,a11=0.f,a12=0.f,a13=0.f;
        int ibase = ic * 10;
#pragma unroll
        for (int ii = 0; ii < 10; ii++) {
            int i = ibase + ii;
            float h0 = s_h[0][i];
            float h1 = s_h[1][i];
            float4 w = *reinterpret_cast<const float4*>(w2 + i * 100 + j0);
            a00 = fmaf(h0, w.x, a00); a01 = fmaf(h0, w.y, a01);
            a02 = fmaf(h0, w.z, a02); a03 = fmaf(h0, w.w, a03);
            a10 = fmaf(h1, w.x, a10); a11 = fmaf(h1, w.y, a11);
            a12 = fmaf(h1, w.z, a12); a13 = fmaf(h1, w.w, a13);
        }
        *reinterpret_cast<float4*>(&s_part[0][ic][j0]) = make_float4(a00,a01,a02,a03);
        *reinterpret_cast<float4*>(&s_part[1][ic][j0]) = make_float4(a10,a11,a12,a13);
    }
    __syncthreads();

    // Phase 2: per-j sum over i-chunks, layer-2 nonlinearity + w3, reduce
    float g0 = 0.f, g1 = 0.f;
    if (tid < 100) {
        float a0 = b2[tid];
        float a1 = a0;
#pragma unroll
        for (int c = 0; c < 10; c++) {
            a0 += s_part[0][c][tid];
            a1 += s_part[1][c][tid];
        }
        float wv = w3[tid];
        g0 = lrelu(a0) * wv;
        g1 = lrelu(a1) * wv;
    }
#pragma unroll
    for (int d = 16; d >= 1; d >>= 1) {
        g0 += __shfl_xor_sync(0xffffffffu, g0, d);
        g1 += __shfl_xor_sync(0xffffffffu, g1, d);
    }
    int wid = tid >> 5, lane = tid & 31;
    if (lane == 0 && wid < 4) { s_red[0][wid] = g0; s_red[1][wid] = g1; }
    __syncthreads();
    if (tid == 0) {
        float bias = b3[0];
        g_table[k0 + 0] = s_red[0][0] + s_red[0][1] + s_red[0][2] + s_red[0][3] + bias;
        g_table[k0 + 1] = s_red[1][0] + s_red[1][1] + s_red[1][2] + s_red[1][3] + bias;
    }
    // Table entries written; let the dependent (scatter) grid spin up.
    pdl_trigger();
}

// ---------------------------------------------------------------------------
// Scatter: one thread per event. Launched with PDL: event loads (t/x/y/p,
// independent of the table) issue BEFORE griddepcontrol.wait, overlapping
// build's tail; table staging + REDs happen after the wait.
// Table staged into SHARED (4KB); 9 bin-values accumulated into
// bin-CONTIGUOUS scratch with 2x red.v4 + 1 scalar RED (3 lanes/event).
// cell = x + W*y + HW*(p + 2*b).
// ---------------------------------------------------------------------------
__global__ __launch_bounds__(256) void scatter_kernel(
    const float* __restrict__ t, const int* __restrict__ x,
    const int* __restrict__ y, const int* __restrict__ p,
    int total)
{
    __shared__ float s_tab[TM];

    int tid = threadIdx.x;
    int e = blockIdx.x * blockDim.x + tid;

    // Independent input loads — no dependence on build's output.
    float tf = 0.f;
    int cell = 0;
    bool valid = (e < total);
    if (valid) {
        tf = t[e];
        int b = e / NN;
        cell = x[e] + WW * y[e] + HW * (p[e] + 2 * b);
    }

    // Wait for build's g_table writes to be visible, then stage the table.
    pdl_wait();
    reinterpret_cast<float4*>(s_tab)[tid & 255] =
        reinterpret_cast<const float4*>(g_table)[tid & 255];
    __syncthreads();

    if (valid) {
        float* dst = g_scratch + (size_t)cell * CPAD;
        const float scale = (float)(TM - 1) * 0.5f;

        float v[9];
#pragma unroll
        for (int i = 0; i < CC; i++) {
            float s = tf - (float)i * 0.125f;     // i/(C-1), C-1 = 8
            float fi = (s + 1.0f) * scale;
            int i0 = (int)fi;
            i0 = max(0, min(i0, TM - 2));
            float fr = fi - (float)i0;
            float f0 = s_tab[i0];
            float f1 = s_tab[i0 + 1];
            v[i] = tf * fmaf(f1 - f0, fr, f0);
        }

        asm volatile("red.global.add.v4.f32 [%0], {%1,%2,%3,%4};"
                     :: "l"(dst), "f"(v[0]), "f"(v[1]), "f"(v[2]), "f"(v[3])
                     : "memory");
        asm volatile("red.global.add.v4.f32 [%0], {%1,%2,%3,%4};"
                     :: "l"(dst + 4), "f"(v[4]), "f"(v[5]), "f"(v[6]), "f"(v[7])
                     : "memory");
        atomicAdd(dst + 8, v[8]);
    }
    // All REDs issued; let transpose spin up.
    pdl_trigger();
}

// ---------------------------------------------------------------------------
// Transpose + scratch reset (PDL: waits, then runs).
// scratch[cell][c] -> out[(q*C + c)*HW + pix], q = cell/HW = p + 2b — exactly
// the reference's concatenated output layout. Cell zeroed after reading so
// the next launch/replay starts clean.
// ---------------------------------------------------------------------------
__global__ __launch_bounds__(256) void transpose_kernel(float* __restrict__ out)
{
    pdl_wait();   // all scatter atomics visible

    int cell = blockIdx.x * blockDim.x + threadIdx.x;   // < NCELLS exactly
    float4* src = reinterpret_cast<float4*>(g_scratch + (size_t)cell * CPAD);
    float4 a  = src[0];
    float4 c4 = src[1];
    float4 c8 = src[2];   // .x = bin 8, rest padding

    float4 z = make_float4(0.f, 0.f, 0.f, 0.f);
    src[0] = z; src[1] = z; src[2] = z;

    int q   = cell / HW;
    int pix = cell - q * HW;
    float* o = out + (size_t)q * CC * HW + pix;

    o[0 * HW] = a.x;  o[1 * HW] = a.y;  o[2 * HW] = a.z;  o[3 * HW] = a.w;
    o[4 * HW] = c4.x; o[5 * HW] = c4.y; o[6 * HW] = c4.z; o[7 * HW] = c4.w;
    o[8 * HW] = c8.x;
}

// ---------------------------------------------------------------------------
// Launch.  metadata order: t, w1, b1, w2, b2, w3, b3, x, y, p
// Scatter and transpose launch with ProgrammaticStreamSerialization so their
// launch processing / independent prologues overlap the predecessor's tail.
// Build keeps default serialization -> cross-replay ordering (prev transpose
// zeroing before this replay's scatter) is fully preserved.
// ---------------------------------------------------------------------------
extern "C" void kernel_launch(void* const* d_in, const int* in_sizes, int n_in,
                              void* d_out, int out_size)
{
    const float* t  = (const float*)d_in[0];
    const float* w1 = (const float*)d_in[1];
    const float* b1 = (const float*)d_in[2];
    const float* w2 = (const float*)d_in[3];
    const float* b2 = (const float*)d_in[4];
    const float* w3 = (const float*)d_in[5];
    const float* b3 = (const float*)d_in[6];
    const int*   x  = (const int*)d_in[7];
    const int*   y  = (const int*)d_in[8];
    const int*   p  = (const int*)d_in[9];
    float* out = (float*)d_out;

    int total = in_sizes[0];          // B*N = 800000

    build_table_kernel<<<TBLK, BT_THREADS>>>(w1, b1, w2, b2, w3, b3);

    cudaLaunchAttribute attr[1];
    attr[0].id = cudaLaunchAttributeProgrammaticStreamSerialization;
    attr[0].val.programmaticStreamSerializationAllowed = 1;

    {
        cudaLaunchConfig_t cfg = {};
        cfg.gridDim  = dim3((total + 255) / 256);
        cfg.blockDim = dim3(256);
        cfg.stream   = 0;
        cfg.attrs    = attr;
        cfg.numAttrs = 1;
        cudaLaunchKernelEx(&cfg, scatter_kernel, t, x, y, p, total);
    }
    {
        cudaLaunchConfig_t cfg = {};
        cfg.gridDim  = dim3(NCELLS / 256);
        cfg.blockDim = dim3(256);
        cfg.stream   = 0;
        cfg.attrs    = attr;
        cfg.numAttrs = 1;
        cudaLaunchKernelEx(&cfg, transpose_kernel, out);
    }
}

// round 17
// speedup vs baseline: 1.4740x; 1.0584x over previous
#include <cuda_runtime.h>
#include <cuda_bf16.h>

// Problem constants (fixed shapes per reference)
#define CC 9
#define HH 180
#define WW 240
#define BB 8
#define NN 100000
#define HW (HH * WW)                   // 43200
#define NUM_VOXELS (2 * CC * HW * BB)  // 6220800
#define NCELLS (BB * 2 * HW)           // 691200 (pixel x polarity x batch)
#define CPAD 12                        // bins padded 9 -> 12 (16B alignment)

// Piecewise-linear table of the scalar MLP f(s), s in [-1, 1].
// Lerp error linear in cell width (verified over 64x span:
// 2.7e-7 @65536 ... 2.7e-5 @1024). TM=512 -> ~5.4e-5, 18x under the gate.
#define TM 512

__device__ float g_table[TM];
// Zero at module load; transpose_kernel re-zeroes each cell after reading,
// so scratch is zero at the start of every launch / graph replay.
__device__ float g_scratch[(size_t)NCELLS * CPAD];   // 33.2 MB

__device__ __forceinline__ float lrelu(float v) {
    return fmaxf(v, 0.1f * v);    // leaky_relu slope 0.1
}

__device__ __forceinline__ void pdl_wait() {
    asm volatile("griddepcontrol.wait;" ::: "memory");
}
__device__ __forceinline__ void pdl_trigger() {
    asm volatile("griddepcontrol.launch_dependents;");
}

// ---------------------------------------------------------------------------
// Table build: ONE BLOCK PER 2 SAMPLES, 256 blocks, phase-decomposed.
// Phase 0: threads 0-99 compute h[sample][i] into smem.
// Phase 1: thread (ic, jq) accumulates a 4-wide j-quad over a 10-wide
//          i-chunk; w2 read directly from global (coalesced, L2-hot).
// Phase 2: per-j sum over chunks, lrelu*w3, butterfly + smem reduce.
// ---------------------------------------------------------------------------
#define BT_THREADS 256
#define TBLK (TM / 2)                  // 256 blocks

__global__ __launch_bounds__(BT_THREADS) void build_table_kernel(
    const float* __restrict__ w1, const float* __restrict__ b1,
    const float* __restrict__ w2, const float* __restrict__ b2,
    const float* __restrict__ w3, const float* __restrict__ b3)
{
    __shared__ float s_h[2][112];          // h[sample][i]
    __shared__ float s_part[2][10][104];   // partial a[sample][i-chunk][j]
    __shared__ float s_red[2][4];

    int tid = threadIdx.x;
    int k0 = blockIdx.x * 2;
    const float step = 2.0f / (float)(TM - 1);
    float s0 = -1.0f + (float)k0 * step;
    float s1 = s0 + step;

    // Phase 0: hidden layer 1 for both samples
    if (tid < 100) {
        float wv = w1[tid], bv = b1[tid];
        s_h[0][tid] = lrelu(fmaf(s0, wv, bv));
        s_h[1][tid] = lrelu(fmaf(s1, wv, bv));
    }
    __syncthreads();

    // Phase 1: partial matvec (250 threads active)
    int jq = tid % 25;
    int ic = tid / 25;
    if (ic < 10) {
        int j0 = jq * 4;
        float a00=0.f,a01=0.f,a02=0.f,a03=0.f;
        float a10=0.f,a11=0.f,a12=0.f,a13=0.f;
        int ibase = ic * 10;
#pragma unroll
        for (int ii = 0; ii < 10; ii++) {
            int i = ibase + ii;
            float h0 = s_h[0][i];
            float h1 = s_h[1][i];
            float4 w = *reinterpret_cast<const float4*>(w2 + i * 100 + j0);
            a00 = fmaf(h0, w.x, a00); a01 = fmaf(h0, w.y, a01);
            a02 = fmaf(h0, w.z, a02); a03 = fmaf(h0, w.w, a03);
            a10 = fmaf(h1, w.x, a10); a11 = fmaf(h1, w.y, a11);
            a12 = fmaf(h1, w.z, a12); a13 = fmaf(h1, w.w, a13);
        }
        *reinterpret_cast<float4*>(&s_part[0][ic][j0]) = make_float4(a00,a01,a02,a03);
        *reinterpret_cast<float4*>(&s_part[1][ic][j0]) = make_float4(a10,a11,a12,a13);
    }
    __syncthreads();

    // Phase 2: per-j sum over i-chunks, layer-2 nonlinearity + w3, reduce
    float g0 = 0.f, g1 = 0.f;
    if (tid < 100) {
        float a0 = b2[tid];
        float a1 = a0;
#pragma unroll
        for (int c = 0; c < 10; c++) {
            a0 += s_part[0][c][tid];
            a1 += s_part[1][c][tid];
        }
        float wv = w3[tid];
        g0 = lrelu(a0) * wv;
        g1 = lrelu(a1) * wv;
    }
#pragma unroll
    for (int d = 16; d >= 1; d >>= 1) {
        g0 += __shfl_xor_sync(0xffffffffu, g0, d);
        g1 += __shfl_xor_sync(0xffffffffu, g1, d);
    }
    int wid = tid >> 5, lane = tid & 31;
    if (lane == 0 && wid < 4) { s_red[0][wid] = g0; s_red[1][wid] = g1; }
    __syncthreads();
    if (tid == 0) {
        float bias = b3[0];
        g_table[k0 + 0] = s_red[0][0] + s_red[0][1] + s_red[0][2] + s_red[0][3] + bias;
        g_table[k0 + 1] = s_red[1][0] + s_red[1][1] + s_red[1][2] + s_red[1][3] + bias;
    }
    // Table entries written; let the dependent (scatter) grid spin up.
    pdl_trigger();
}

// ---------------------------------------------------------------------------
// Scatter: TWO events per thread, vectorized float2/int2 loads (events 2e,
// 2e+1 always share a batch: NN is even, so an odd global index never sits
// on a batch boundary). PDL: the event loads (independent of the table)
// issue BEFORE griddepcontrol.wait, overlapping build's tail.
// Table staged into SHARED (2KB); per event 9 bin-values accumulated into
// bin-CONTIGUOUS scratch with 2x red.v4 + 1 scalar RED (3 lanes/event).
// cell = x + W*y + HW*(p + 2*b).
// ---------------------------------------------------------------------------
__device__ __forceinline__ void scatter_one(
    const float* __restrict__ s_tab, float tf, int cell)
{
    float* dst = g_scratch + (size_t)cell * CPAD;
    const float scale = (float)(TM - 1) * 0.5f;

    float v[9];
#pragma unroll
    for (int i = 0; i < CC; i++) {
        float s = tf - (float)i * 0.125f;     // i/(C-1), C-1 = 8
        float fi = (s + 1.0f) * scale;
        int i0 = (int)fi;
        i0 = max(0, min(i0, TM - 2));
        float fr = fi - (float)i0;
        float f0 = s_tab[i0];
        float f1 = s_tab[i0 + 1];
        v[i] = tf * fmaf(f1 - f0, fr, f0);
    }

    asm volatile("red.global.add.v4.f32 [%0], {%1,%2,%3,%4};"
                 :: "l"(dst), "f"(v[0]), "f"(v[1]), "f"(v[2]), "f"(v[3])
                 : "memory");
    asm volatile("red.global.add.v4.f32 [%0], {%1,%2,%3,%4};"
                 :: "l"(dst + 4), "f"(v[4]), "f"(v[5]), "f"(v[6]), "f"(v[7])
                 : "memory");
    atomicAdd(dst + 8, v[8]);
}

__global__ __launch_bounds__(256) void scatter_kernel(
    const float* __restrict__ t, const int* __restrict__ x,
    const int* __restrict__ y, const int* __restrict__ p,
    int npairs)
{
    __shared__ float s_tab[TM];

    int tid = threadIdx.x;
    int pe = blockIdx.x * blockDim.x + tid;   // pair index

    // Independent input loads — no dependence on build's output.
    float2 t2 = make_float2(0.f, 0.f);
    int cell0 = 0, cell1 = 0;
    bool valid = (pe < npairs);
    if (valid) {
        t2 = reinterpret_cast<const float2*>(t)[pe];
        int2 x2 = reinterpret_cast<const int2*>(x)[pe];
        int2 y2 = reinterpret_cast<const int2*>(y)[pe];
        int2 p2 = reinterpret_cast<const int2*>(p)[pe];
        int b = (2 * pe) / NN;                 // same b for both events
        cell0 = x2.x + WW * y2.x + HW * (p2.x + 2 * b);
        cell1 = x2.y + WW * y2.y + HW * (p2.y + 2 * b);
    }

    // Wait for build's g_table writes, then stage the 2KB table.
    pdl_wait();
    if (tid < TM / 4)
        reinterpret_cast<float4*>(s_tab)[tid] =
            reinterpret_cast<const float4*>(g_table)[tid];
    __syncthreads();

    if (valid) {
        scatter_one(s_tab, t2.x, cell0);
        scatter_one(s_tab, t2.y, cell1);
    }
    // All REDs issued; let transpose spin up.
    pdl_trigger();
}

// ---------------------------------------------------------------------------
// Transpose + scratch reset (PDL: waits, then runs).
// scratch[cell][c] -> out[(q*C + c)*HW + pix], q = cell/HW = p + 2b — exactly
// the reference's concatenated output layout. Cell zeroed after reading so
// the next launch/replay starts clean (measured ~free: write-back overlaps).
// ---------------------------------------------------------------------------
__global__ __launch_bounds__(256) void transpose_kernel(float* __restrict__ out)
{
    pdl_wait();   // all scatter atomics visible

    int cell = blockIdx.x * blockDim.x + threadIdx.x;   // < NCELLS exactly
    float4* src = reinterpret_cast<float4*>(g_scratch + (size_t)cell * CPAD);
    float4 a  = src[0];
    float4 c4 = src[1];
    float4 c8 = src[2];   // .x = bin 8, rest padding

    float4 z = make_float4(0.f, 0.f, 0.f, 0.f);
    src[0] = z; src[1] = z; src[2] = z;

    int q   = cell / HW;
    int pix = cell - q * HW;
    float* o = out + (size_t)q * CC * HW + pix;

    o[0 * HW] = a.x;  o[1 * HW] = a.y;  o[2 * HW] = a.z;  o[3 * HW] = a.w;
    o[4 * HW] = c4.x; o[5 * HW] = c4.y; o[6 * HW] = c4.z; o[7 * HW] = c4.w;
    o[8 * HW] = c8.x;
}

// ---------------------------------------------------------------------------
// Launch.  metadata order: t, w1, b1, w2, b2, w3, b3, x, y, p
// Scatter and transpose launch with ProgrammaticStreamSerialization; build
// keeps default serialization so cross-replay ordering (prev transpose's
// zeroing before this replay's scatter) is preserved.
// ---------------------------------------------------------------------------
extern "C" void kernel_launch(void* const* d_in, const int* in_sizes, int n_in,
                              void* d_out, int out_size)
{
    const float* t  = (const float*)d_in[0];
    const float* w1 = (const float*)d_in[1];
    const float* b1 = (const float*)d_in[2];
    const float* w2 = (const float*)d_in[3];
    const float* b2 = (const float*)d_in[4];
    const float* w3 = (const float*)d_in[5];
    const float* b3 = (const float*)d_in[6];
    const int*   x  = (const int*)d_in[7];
    const int*   y  = (const int*)d_in[8];
    const int*   p  = (const int*)d_in[9];
    float* out = (float*)d_out;

    int total  = in_sizes[0];         // B*N = 800000 (even)
    int npairs = total / 2;           // 400000

    build_table_kernel<<<TBLK, BT_THREADS>>>(w1, b1, w2, b2, w3, b3);

    cudaLaunchAttribute attr[1];
    attr[0].id = cudaLaunchAttributeProgrammaticStreamSerialization;
    attr[0].val.programmaticStreamSerializationAllowed = 1;

    {
        cudaLaunchConfig_t cfg = {};
        cfg.gridDim  = dim3((npairs + 255) / 256);
        cfg.blockDim = dim3(256);
        cfg.stream   = 0;
        cfg.attrs    = attr;
        cfg.numAttrs = 1;
        cudaLaunchKernelEx(&cfg, scatter_kernel, t, x, y, p, npairs);
    }
    {
        cudaLaunchConfig_t cfg = {};
        cfg.gridDim  = dim3(NCELLS / 256);
        cfg.blockDim = dim3(256);
        cfg.stream   = 0;
        cfg.attrs    = attr;
        cfg.numAttrs = 1;
        cudaLaunchKernelEx(&cfg, transpose_kernel, out);
    }
}